// round 8
// baseline (speedup 1.0000x reference)
#include <cuda_runtime.h>
#include <cuda_bf16.h>
#include <cstdint>

// MatrixExpander: out(16,16,512,512) = kron(A(16,16,64,64), ones(8,8)), fp32.
//
// R8: CTA-per-tile TMA bulk store (R7 winner) + 8x smem-source reuse.
// Tile c's 16 KB output span is 8 identical copies of a 2 KB expanded row
// (expanded[j] = A[c*64 + j/8]). Fill ONLY the 2 KB row in smem
// (conflict-free: thread t -> float4 slot t), then issue EIGHT 2 KB
// cp.async.bulk stores from the SAME smem source to the 8 output rows.
//   - STS traffic: 256 MB -> 32 MB (L1 crossbar was the top consumer at 66%)
//   - 128-thread CTAs -> more resident CTAs -> deeper bulk-store MLP

__device__ __forceinline__ uint32_t smem_u32(const void* p) {
    uint32_t a;
    asm("{ .reg .u64 t; cvta.to.shared.u64 t, %1; cvt.u32.u64 %0, t; }"
        : "=r"(a) : "l"(p));
    return a;
}

__global__ __launch_bounds__(128)
void expander_tma_r8_kernel(const float* __restrict__ A, float* __restrict__ out)
{
    __shared__ __align__(128) float4 row[128];   // 2 KB expanded row

    const uint32_t c = blockIdx.x;   // tile id in [0, 16384)
    const uint32_t t = threadIdx.x;  // [0, 128)

    // Slot t covers output cols [4t, 4t+4) -> A col t>>1 (adjacent-thread
    // broadcast). One scalar load, one splat, one conflict-free STS.128.
    const float v = __ldg(A + (c << 6) + (t >> 1));
    row[t] = make_float4(v, v, v, v);

    __syncthreads();

    if (t == 0) {
        // Order generic-proxy STS before async-proxy bulk reads.
        asm volatile("fence.proxy.async.shared::cta;" ::: "memory");
        const uint32_t s = smem_u32(row);
        float* dst = out + ((size_t)c << 12);   // c * 4096 floats
        #pragma unroll
        for (int r = 0; r < 8; ++r) {
            asm volatile(
                "cp.async.bulk.global.shared::cta.bulk_group [%0], [%1], %2;"
                :: "l"(dst + (r << 9)), "r"(s), "n"(2048) : "memory");
        }
        asm volatile("cp.async.bulk.commit_group;" ::: "memory");
        asm volatile("cp.async.bulk.wait_group 0;" ::: "memory");
    }
}

extern "C" void kernel_launch(void* const* d_in, const int* in_sizes, int n_in,
                              void* d_out, int out_size)
{
    const float* A = (const float*)d_in[0];   // (16,16,64,64) fp32
    float* out = (float*)d_out;               // (16,16,512,512) fp32

    // 16384 tiles; each CTA emits 8 x 2 KB bulk stores = 16 KB
    expander_tma_r8_kernel<<<16384, 128>>>(A, out);
}